// round 1
// baseline (speedup 1.0000x reference)
#include <cuda_runtime.h>
#include <math.h>

#define N_TOT   4096
#define N_UP    2048
#define HIDDEN  32
#define BOX     10.0f
#define TBL     4096
#define SMAX    25.0f        // r_cut^2 = 5^2
#define CHUNK   128
#define THREADS 256

// Precomputed f(s) tables: [0]=same-spin net, [1]=diff-spin net.
// Each entry: (value, slope-to-next-entry) for linear interpolation.
__device__ __align__(16) float2 g_tab[2][TBL];

// ---------------------------------------------------------------------------
// Evaluate the decayed MLP at squared distance s (reference-faithful math).
// ---------------------------------------------------------------------------
__device__ float eval_net(float s,
                          const float* __restrict__ w1,
                          const float* __restrict__ b1,
                          const float* __restrict__ wo,
                          const float* __restrict__ bo) {
    float r  = sqrtf(s + 1e-15f);
    float xn = fminf(r * (1.0f / 5.0f), 1.0f - 1e-5f);   // clip(x/x_cut, 0, 1-1e-5); r>=0
    float u  = 1.0f - xn * xn;                            // > 0 always (>= ~2e-5)
    float decay = expf(1.0f - 1.0f / u);                  // underflows to 0 near cutoff
    float acc = bo[0];
    #pragma unroll
    for (int k = 0; k < HIDDEN; k++) {
        float z = decay * w1[k] + b1[k];
        float h = z / (1.0f + expf(-z));                  // swish
        acc += h * wo[k];
    }
    return acc * decay;
}

__global__ void build_tables(const float* sw1, const float* sb1,
                             const float* swo, const float* sbo,
                             const float* dw1, const float* db1,
                             const float* dwo, const float* dbo) {
    int g = blockIdx.x * blockDim.x + threadIdx.x;
    if (g >= 2 * TBL) return;
    int net = g / TBL;
    int k   = g % TBL;
    const float* w1 = net ? dw1 : sw1;
    const float* b1 = net ? db1 : sb1;
    const float* wo = net ? dwo : swo;
    const float* bo = net ? dbo : sbo;
    const float h = SMAX / (float)(TBL - 1);
    float f0 = eval_net((float)k * h, w1, b1, wo, bo);
    float f1 = (k + 1 < TBL) ? eval_net((float)(k + 1) * h, w1, b1, wo, bo) : f0;
    g_tab[net][k] = make_float2(f0, f1 - f0);
}

// out = rs  (d_out is poisoned by the harness; atomics accumulate on top)
__global__ void init_out(const float* __restrict__ rs, float* __restrict__ out) {
    int i = blockIdx.x * blockDim.x + threadIdx.x;
    if (i < N_TOT * 3) out[i] = rs[i];
}

// ---------------------------------------------------------------------------
// Main pairwise kernel.
// grid.x = 16 row blocks (256 rows each, one per thread)
// grid.y = 32 j-chunks  (128 columns each)
// Row block and j-chunk each lie entirely in one spin half -> one table / CTA.
// ---------------------------------------------------------------------------
__global__ void __launch_bounds__(THREADS)
backflow_kernel(const float* __restrict__ rs, float* __restrict__ out) {
    __shared__ __align__(16) float2 s_tab[TBL];
    __shared__ float sjx[CHUNK], sjy[CHUNK], sjz[CHUNK];

    const int tid    = threadIdx.x;
    const int rowBlk = blockIdx.x;       // 0..15   (rows rowBlk*256 ..)
    const int jBlk   = blockIdx.y;       // 0..31   (cols jBlk*128 ..)
    const int i      = rowBlk * THREADS + tid;
    const int j0     = jBlk * CHUNK;

    // same-spin if both halves match
    const int net = ((rowBlk < 8) == (jBlk < 16)) ? 0 : 1;

    // stage table (32 KB) into shared
    {
        const float4* src = (const float4*)g_tab[net];
        float4*       dst = (float4*)s_tab;
        #pragma unroll
        for (int t = tid; t < TBL / 2; t += THREADS) dst[t] = src[t];
    }
    // stage this chunk's j coordinates
    if (tid < CHUNK) {
        int j = j0 + tid;
        sjx[tid] = rs[3 * j + 0];
        sjy[tid] = rs[3 * j + 1];
        sjz[tid] = rs[3 * j + 2];
    }
    __syncthreads();

    const float xi = rs[3 * i + 0];
    const float yi = rs[3 * i + 1];
    const float zi = rs[3 * i + 2];

    float ax = 0.0f, ay = 0.0f, az = 0.0f;
    const float scale = (float)(TBL - 1) / SMAX;
    const float tmax  = (float)(TBL - 1) - 1e-3f;

    #pragma unroll 8
    for (int jj = 0; jj < CHUNK; jj++) {
        float dx = xi - sjx[jj];
        float dy = yi - sjy[jj];
        float dz = zi - sjz[jj];
        // minimum image: d -= BOX * rint(d / BOX)
        dx = fmaf(-BOX, rintf(dx * (1.0f / BOX)), dx);
        dy = fmaf(-BOX, rintf(dy * (1.0f / BOX)), dy);
        dz = fmaf(-BOX, rintf(dz * (1.0f / BOX)), dz);

        float s = fmaf(dx, dx, fmaf(dy, dy, dz * dz));
        // table lookup; beyond cutoff the clamped lerp lands on an exact 0.
        float t = fminf(s * scale, tmax);
        int   k = (int)t;
        float fr = t - (float)k;
        float2 tv = s_tab[k];
        float f = fmaf(fr, tv.y, tv.x);

        ax = fmaf(f, dx, ax);
        ay = fmaf(f, dy, ay);
        az = fmaf(f, dz, az);
    }

    atomicAdd(&out[3 * i + 0], ax);
    atomicAdd(&out[3 * i + 1], ay);
    atomicAdd(&out[3 * i + 2], az);
}

extern "C" void kernel_launch(void* const* d_in, const int* in_sizes, int n_in,
                              void* d_out, int out_size) {
    const float* rs  = (const float*)d_in[0];
    const float* sw1 = (const float*)d_in[1];
    const float* sb1 = (const float*)d_in[2];
    const float* swo = (const float*)d_in[3];
    const float* sbo = (const float*)d_in[4];
    const float* dw1 = (const float*)d_in[5];
    const float* db1 = (const float*)d_in[6];
    const float* dwo = (const float*)d_in[7];
    const float* dbo = (const float*)d_in[8];
    float* out = (float*)d_out;

    build_tables<<<(2 * TBL + 255) / 256, 256>>>(sw1, sb1, swo, sbo,
                                                 dw1, db1, dwo, dbo);
    init_out<<<(N_TOT * 3 + 255) / 256, 256>>>(rs, out);

    dim3 grid(N_TOT / THREADS, N_TOT / CHUNK);   // (16, 32)
    backflow_kernel<<<grid, THREADS>>>(rs, out);
}

// round 2
// speedup vs baseline: 2.0579x; 2.0579x over previous
#include <cuda_runtime.h>
#include <math.h>

#define N_TOT   4096
#define N_UP    2048
#define HIDDEN  32
#define BOX     10.0f
#define TBL     2048
#define SMAX    25.0f        // r_cut^2 = 5^2
#define CHUNK   128
#define THREADS 256
#define INIT_CTAS 16         // CTAs in build kernel dedicated to out=rs init

// Precomputed f(s) tables: [0]=same-spin net, [1]=diff-spin net.
// Each entry: (value, slope-to-next-entry) for linear interpolation.
__device__ __align__(16) float2 g_tab[2][TBL];

// ---------------------------------------------------------------------------
// Decay envelope at squared distance s (reference-faithful math).
// ---------------------------------------------------------------------------
__device__ __forceinline__ float decay_of_s(float s) {
    float r  = sqrtf(s + 1e-15f);
    float xn = fminf(r * (1.0f / 5.0f), 1.0f - 1e-5f);   // clip(x/x_cut, 0, 1-1e-5)
    float u  = 1.0f - xn * xn;                            // >= ~2e-5
    return expf(1.0f - 1.0f / u);                         // -> 0 at cutoff
}

// Per-lane contribution of hidden unit `lane` at envelope value `decay`.
__device__ __forceinline__ float unit_contrib(float decay, float w1, float b1, float wo) {
    float z = fmaf(decay, w1, b1);
    float h = z / (1.0f + expf(-z));                      // swish
    return h * wo;
}

// ---------------------------------------------------------------------------
// Fused: build both f(s) tables (one warp per table entry, one lane per
// hidden unit) AND initialize out = rs (first INIT_CTAS blocks).
// ---------------------------------------------------------------------------
__global__ void __launch_bounds__(THREADS)
build_and_init(const float* __restrict__ rs, float* __restrict__ out,
               const float* __restrict__ sw1, const float* __restrict__ sb1,
               const float* __restrict__ swo, const float* __restrict__ sbo,
               const float* __restrict__ dw1, const float* __restrict__ db1,
               const float* __restrict__ dwo, const float* __restrict__ dbo) {
    const int bid = blockIdx.x;
    const int tid = threadIdx.x;

    if (bid < INIT_CTAS) {
        // out = rs (12288 floats over 16*256 threads -> 3 each)
        for (int i = bid * THREADS + tid; i < N_TOT * 3; i += INIT_CTAS * THREADS)
            out[i] = rs[i];
        return;
    }

    // table build: warps (bid-INIT_CTAS)*8 + wid -> entries 0..2*TBL-1
    const int wglob = (bid - INIT_CTAS) * (THREADS / 32) + (tid >> 5);
    if (wglob >= 2 * TBL) return;
    const int net  = wglob / TBL;        // 0 = same, 1 = diff
    const int k    = wglob % TBL;
    const int lane = tid & 31;           // == hidden unit index (HIDDEN==32)

    const float w1 = net ? dw1[lane] : sw1[lane];
    const float b1 = net ? db1[lane] : sb1[lane];
    const float wo = net ? dwo[lane] : swo[lane];
    const float bo = net ? dbo[0]    : sbo[0];

    const float h = SMAX / (float)(TBL - 1);
    const float d0 = decay_of_s((float)k * h);
    const float d1 = decay_of_s((float)(k + 1) * h);   // past-end: decay==0 -> f==0

    float a0 = unit_contrib(d0, w1, b1, wo);
    float a1 = unit_contrib(d1, w1, b1, wo);
    #pragma unroll
    for (int off = 16; off > 0; off >>= 1) {
        a0 += __shfl_xor_sync(0xFFFFFFFFu, a0, off);
        a1 += __shfl_xor_sync(0xFFFFFFFFu, a1, off);
    }
    if (lane == 0) {
        float f0 = (a0 + bo) * d0;
        float f1 = (a1 + bo) * d1;
        g_tab[net][k] = make_float2(f0, f1 - f0);
    }
}

// ---------------------------------------------------------------------------
// Main pairwise kernel.
// grid.x = 16 row blocks (256 rows each, one per thread)
// grid.y = 32 j-chunks  (128 columns each)
// Row block and j-chunk each lie entirely in one spin half -> one table / CTA.
// ---------------------------------------------------------------------------
__global__ void __launch_bounds__(THREADS)
backflow_kernel(const float* __restrict__ rs, float* __restrict__ out) {
    __shared__ __align__(16) float2 s_tab[TBL];
    __shared__ float sjx[CHUNK], sjy[CHUNK], sjz[CHUNK];

    const int tid    = threadIdx.x;
    const int rowBlk = blockIdx.x;       // 0..15   (rows rowBlk*256 ..)
    const int jBlk   = blockIdx.y;       // 0..31   (cols jBlk*128 ..)
    const int i      = rowBlk * THREADS + tid;
    const int j0     = jBlk * CHUNK;

    // same-spin if both halves match
    const int net = ((rowBlk < 8) == (jBlk < 16)) ? 0 : 1;

    // stage table (16 KB) into shared
    {
        const float4* src = (const float4*)g_tab[net];
        float4*       dst = (float4*)s_tab;
        #pragma unroll
        for (int t = tid; t < TBL / 2; t += THREADS) dst[t] = src[t];
    }
    // stage this chunk's j coordinates
    if (tid < CHUNK) {
        int j = j0 + tid;
        sjx[tid] = rs[3 * j + 0];
        sjy[tid] = rs[3 * j + 1];
        sjz[tid] = rs[3 * j + 2];
    }
    __syncthreads();

    const float xi = rs[3 * i + 0];
    const float yi = rs[3 * i + 1];
    const float zi = rs[3 * i + 2];

    float ax = 0.0f, ay = 0.0f, az = 0.0f;
    const float scale = (float)(TBL - 1) / SMAX;
    const float tmax  = (float)(TBL - 1) - 1e-3f;

    #pragma unroll 8
    for (int jj = 0; jj < CHUNK; jj++) {
        float dx = xi - sjx[jj];
        float dy = yi - sjy[jj];
        float dz = zi - sjz[jj];
        // minimum image: d -= BOX * rint(d / BOX)
        dx = fmaf(-BOX, rintf(dx * (1.0f / BOX)), dx);
        dy = fmaf(-BOX, rintf(dy * (1.0f / BOX)), dy);
        dz = fmaf(-BOX, rintf(dz * (1.0f / BOX)), dz);

        float s = fmaf(dx, dx, fmaf(dy, dy, dz * dz));
        // table lookup; beyond cutoff the clamped lerp lands on an exact 0.
        float t = fminf(s * scale, tmax);
        int   k = (int)t;
        float fr = t - (float)k;
        float2 tv = s_tab[k];
        float f = fmaf(fr, tv.y, tv.x);

        ax = fmaf(f, dx, ax);
        ay = fmaf(f, dy, ay);
        az = fmaf(f, dz, az);
    }

    atomicAdd(&out[3 * i + 0], ax);
    atomicAdd(&out[3 * i + 1], ay);
    atomicAdd(&out[3 * i + 2], az);
}

extern "C" void kernel_launch(void* const* d_in, const int* in_sizes, int n_in,
                              void* d_out, int out_size) {
    const float* rs  = (const float*)d_in[0];
    const float* sw1 = (const float*)d_in[1];
    const float* sb1 = (const float*)d_in[2];
    const float* swo = (const float*)d_in[3];
    const float* sbo = (const float*)d_in[4];
    const float* dw1 = (const float*)d_in[5];
    const float* db1 = (const float*)d_in[6];
    const float* dwo = (const float*)d_in[7];
    const float* dbo = (const float*)d_in[8];
    float* out = (float*)d_out;

    // table warps: 2*TBL entries, 8 warps/CTA -> 512 CTAs, + 16 init CTAs
    const int buildGrid = INIT_CTAS + (2 * TBL) / (THREADS / 32);
    build_and_init<<<buildGrid, THREADS>>>(rs, out,
                                           sw1, sb1, swo, sbo,
                                           dw1, db1, dwo, dbo);

    dim3 grid(N_TOT / THREADS, N_TOT / CHUNK);   // (16, 32)
    backflow_kernel<<<grid, THREADS>>>(rs, out);
}

// round 3
// speedup vs baseline: 2.1980x; 1.0681x over previous
#include <cuda_runtime.h>
#include <math.h>

#define N_TOT   4096
#define N_UP    2048
#define HIDDEN  32
#define BOX     10.0f
#define TBL     1024
#define SMAX    25.0f        // r_cut^2 = 5^2
#define CHUNK   64
#define THREADS 256
#define INIT_CTAS 16         // CTAs in build kernel dedicated to out=rs init

// Precomputed f(s) tables: [0]=same-spin net, [1]=diff-spin net.
// Each entry: (value, slope-to-next-entry) for linear interpolation.
__device__ __align__(16) float2 g_tab[2][TBL];

// ---------------------------------------------------------------------------
// Decay envelope at squared distance s (reference-faithful math).
// ---------------------------------------------------------------------------
__device__ __forceinline__ float decay_of_s(float s) {
    float r  = sqrtf(s + 1e-15f);
    float xn = fminf(r * (1.0f / 5.0f), 1.0f - 1e-5f);   // clip(x/x_cut, 0, 1-1e-5)
    float u  = 1.0f - xn * xn;                            // >= ~2e-5
    return expf(1.0f - 1.0f / u);                         // -> 0 at cutoff
}

// Per-lane contribution of hidden unit `lane` at envelope value `decay`.
__device__ __forceinline__ float unit_contrib(float decay, float w1, float b1, float wo) {
    float z = fmaf(decay, w1, b1);
    float h = z / (1.0f + expf(-z));                      // swish
    return h * wo;
}

// ---------------------------------------------------------------------------
// Fused: build both f(s) tables (one warp per table entry, one lane per
// hidden unit) AND initialize out = rs (first INIT_CTAS blocks).
// ---------------------------------------------------------------------------
__global__ void __launch_bounds__(THREADS)
build_and_init(const float* __restrict__ rs, float* __restrict__ out,
               const float* __restrict__ sw1, const float* __restrict__ sb1,
               const float* __restrict__ swo, const float* __restrict__ sbo,
               const float* __restrict__ dw1, const float* __restrict__ db1,
               const float* __restrict__ dwo, const float* __restrict__ dbo) {
    const int bid = blockIdx.x;
    const int tid = threadIdx.x;

    if (bid < INIT_CTAS) {
        // out = rs (12288 floats over 16*256 threads -> 3 each)
        for (int i = bid * THREADS + tid; i < N_TOT * 3; i += INIT_CTAS * THREADS)
            out[i] = rs[i];
        return;
    }

    // table build: warps (bid-INIT_CTAS)*8 + wid -> entries 0..2*TBL-1
    const int wglob = (bid - INIT_CTAS) * (THREADS / 32) + (tid >> 5);
    if (wglob >= 2 * TBL) return;
    const int net  = wglob / TBL;        // 0 = same, 1 = diff
    const int k    = wglob % TBL;
    const int lane = tid & 31;           // == hidden unit index (HIDDEN==32)

    const float w1 = net ? dw1[lane] : sw1[lane];
    const float b1 = net ? db1[lane] : sb1[lane];
    const float wo = net ? dwo[lane] : swo[lane];
    const float bo = net ? dbo[0]    : sbo[0];

    const float h = SMAX / (float)(TBL - 1);
    const float d0 = decay_of_s((float)k * h);
    const float d1 = decay_of_s((float)(k + 1) * h);   // past-end: decay==0 -> f==0

    float a0 = unit_contrib(d0, w1, b1, wo);
    float a1 = unit_contrib(d1, w1, b1, wo);
    #pragma unroll
    for (int off = 16; off > 0; off >>= 1) {
        a0 += __shfl_xor_sync(0xFFFFFFFFu, a0, off);
        a1 += __shfl_xor_sync(0xFFFFFFFFu, a1, off);
    }
    if (lane == 0) {
        float f0 = (a0 + bo) * d0;
        float f1 = (a1 + bo) * d1;
        g_tab[net][k] = make_float2(f0, f1 - f0);
    }
}

// ---------------------------------------------------------------------------
// Main pairwise kernel.
// grid.x = 16 row blocks (256 rows each, one per thread)
// grid.y = 64 j-chunks  (64 columns each)
// Row block and j-chunk each lie entirely in one spin half -> one table / CTA.
// ---------------------------------------------------------------------------
__global__ void __launch_bounds__(THREADS)
backflow_kernel(const float* __restrict__ rs, float* __restrict__ out) {
    __shared__ __align__(16) float2 s_tab[TBL];
    __shared__ __align__(16) float4 sj[CHUNK];

    const int tid    = threadIdx.x;
    const int rowBlk = blockIdx.x;       // 0..15   (rows rowBlk*256 ..)
    const int jBlk   = blockIdx.y;       // 0..63   (cols jBlk*64 ..)
    const int i      = rowBlk * THREADS + tid;
    const int j0     = jBlk * CHUNK;

    // same-spin if both halves match
    const int net = ((rowBlk < 8) == (jBlk < 32)) ? 0 : 1;

    // stage table (8 KB) into shared
    {
        const float4* src = (const float4*)g_tab[net];
        float4*       dst = (float4*)s_tab;
        #pragma unroll
        for (int t = tid; t < TBL / 2; t += THREADS) dst[t] = src[t];
    }
    // stage this chunk's j coordinates (packed xyz_)
    if (tid < CHUNK) {
        int j = j0 + tid;
        sj[tid] = make_float4(rs[3 * j + 0], rs[3 * j + 1], rs[3 * j + 2], 0.0f);
    }
    __syncthreads();

    const float xi = rs[3 * i + 0];
    const float yi = rs[3 * i + 1];
    const float zi = rs[3 * i + 2];

    float ax = 0.0f, ay = 0.0f, az = 0.0f;
    const float scale = (float)(TBL - 1) / SMAX;
    const float tmax  = (float)(TBL - 1) - 1e-3f;

    #pragma unroll 8
    for (int jj = 0; jj < CHUNK; jj++) {
        const float4 p = sj[jj];           // broadcast LDS.128
        float dx = xi - p.x;
        float dy = yi - p.y;
        float dz = zi - p.z;
        // minimum image: d -= BOX * rint(d / BOX)
        dx = fmaf(-BOX, rintf(dx * (1.0f / BOX)), dx);
        dy = fmaf(-BOX, rintf(dy * (1.0f / BOX)), dy);
        dz = fmaf(-BOX, rintf(dz * (1.0f / BOX)), dz);

        float s = fmaf(dx, dx, fmaf(dy, dy, dz * dz));
        // table lookup; beyond cutoff the clamped lerp lands on an exact 0.
        float t = fminf(s * scale, tmax);
        int   k = (int)t;
        float fr = t - (float)k;
        float2 tv = s_tab[k];
        float f = fmaf(fr, tv.y, tv.x);

        ax = fmaf(f, dx, ax);
        ay = fmaf(f, dy, ay);
        az = fmaf(f, dz, az);
    }

    atomicAdd(&out[3 * i + 0], ax);
    atomicAdd(&out[3 * i + 1], ay);
    atomicAdd(&out[3 * i + 2], az);
}

extern "C" void kernel_launch(void* const* d_in, const int* in_sizes, int n_in,
                              void* d_out, int out_size) {
    const float* rs  = (const float*)d_in[0];
    const float* sw1 = (const float*)d_in[1];
    const float* sb1 = (const float*)d_in[2];
    const float* swo = (const float*)d_in[3];
    const float* sbo = (const float*)d_in[4];
    const float* dw1 = (const float*)d_in[5];
    const float* db1 = (const float*)d_in[6];
    const float* dwo = (const float*)d_in[7];
    const float* dbo = (const float*)d_in[8];
    float* out = (float*)d_out;

    // table warps: 2*TBL entries, 8 warps/CTA -> 256 CTAs, + 16 init CTAs
    const int buildGrid = INIT_CTAS + (2 * TBL) / (THREADS / 32);
    build_and_init<<<buildGrid, THREADS>>>(rs, out,
                                           sw1, sb1, swo, sbo,
                                           dw1, db1, dwo, dbo);

    dim3 grid(N_TOT / THREADS, N_TOT / CHUNK);   // (16, 64)
    backflow_kernel<<<grid, THREADS>>>(rs, out);
}

// round 4
// speedup vs baseline: 2.2261x; 1.0128x over previous
#include <cuda_runtime.h>
#include <cuda_fp16.h>
#include <math.h>

#define N_TOT   4096
#define N_UP    2048
#define HIDDEN  32
#define BOX     10.0f
#define TBL     2048
#define SMAX    25.0f        // r_cut^2 = 5^2
#define CHUNK   64
#define THREADS 256
#define INIT_CTAS 16         // CTAs in build kernel dedicated to out=rs init

// Precomputed f(s) tables: [0]=same-spin net, [1]=diff-spin net.
// Each half2 entry: (value, slope-to-next-entry) for linear interpolation.
__device__ __align__(16) __half2 g_tab[2][TBL];

// ---------------------------------------------------------------------------
// Decay envelope at squared distance s (reference-faithful math).
// ---------------------------------------------------------------------------
__device__ __forceinline__ float decay_of_s(float s) {
    float r  = sqrtf(s + 1e-15f);
    float xn = fminf(r * (1.0f / 5.0f), 1.0f - 1e-5f);   // clip(x/x_cut, 0, 1-1e-5)
    float u  = 1.0f - xn * xn;                            // >= ~2e-5
    return expf(1.0f - 1.0f / u);                         // -> 0 at cutoff
}

// Per-lane contribution of hidden unit `lane` at envelope value `decay`.
__device__ __forceinline__ float unit_contrib(float decay, float w1, float b1, float wo) {
    float z = fmaf(decay, w1, b1);
    float h = z / (1.0f + expf(-z));                      // swish
    return h * wo;
}

// ---------------------------------------------------------------------------
// Fused: build both f(s) tables (one warp per table entry, one lane per
// hidden unit) AND initialize out = rs (first INIT_CTAS blocks).
// ---------------------------------------------------------------------------
__global__ void __launch_bounds__(THREADS)
build_and_init(const float* __restrict__ rs, float* __restrict__ out,
               const float* __restrict__ sw1, const float* __restrict__ sb1,
               const float* __restrict__ swo, const float* __restrict__ sbo,
               const float* __restrict__ dw1, const float* __restrict__ db1,
               const float* __restrict__ dwo, const float* __restrict__ dbo) {
    const int bid = blockIdx.x;
    const int tid = threadIdx.x;

    if (bid < INIT_CTAS) {
        // out = rs (12288 floats over 16*256 threads -> 3 each)
        for (int i = bid * THREADS + tid; i < N_TOT * 3; i += INIT_CTAS * THREADS)
            out[i] = rs[i];
        return;
    }

    // table build: warps (bid-INIT_CTAS)*8 + wid -> entries 0..2*TBL-1
    const int wglob = (bid - INIT_CTAS) * (THREADS / 32) + (tid >> 5);
    if (wglob >= 2 * TBL) return;
    const int net  = wglob / TBL;        // 0 = same, 1 = diff
    const int k    = wglob % TBL;
    const int lane = tid & 31;           // == hidden unit index (HIDDEN==32)

    const float w1 = net ? dw1[lane] : sw1[lane];
    const float b1 = net ? db1[lane] : sb1[lane];
    const float wo = net ? dwo[lane] : swo[lane];
    const float bo = net ? dbo[0]    : sbo[0];

    const float h = SMAX / (float)(TBL - 1);
    const float d0 = decay_of_s((float)k * h);
    const float d1 = decay_of_s((float)(k + 1) * h);   // past-end: decay==0 -> f==0

    float a0 = unit_contrib(d0, w1, b1, wo);
    float a1 = unit_contrib(d1, w1, b1, wo);
    #pragma unroll
    for (int off = 16; off > 0; off >>= 1) {
        a0 += __shfl_xor_sync(0xFFFFFFFFu, a0, off);
        a1 += __shfl_xor_sync(0xFFFFFFFFu, a1, off);
    }
    if (lane == 0) {
        float f0 = (a0 + bo) * d0;
        float f1 = (a1 + bo) * d1;
        g_tab[net][k] = __floats2half2_rn(f0, f1 - f0);
    }
}

// ---------------------------------------------------------------------------
// Main pairwise kernel.
// grid.x = 16 row blocks (256 rows each, one per thread)
// grid.y = 64 j-chunks  (64 columns each)
// Row block and j-chunk each lie entirely in one spin half -> one table / CTA.
// ---------------------------------------------------------------------------
__global__ void __launch_bounds__(THREADS)
backflow_kernel(const float* __restrict__ rs, float* __restrict__ out) {
    __shared__ __align__(16) __half2 s_tab[TBL];          // 8 KB
    __shared__ __align__(16) float4  sj[CHUNK];

    const int tid    = threadIdx.x;
    const int rowBlk = blockIdx.x;       // 0..15   (rows rowBlk*256 ..)
    const int jBlk   = blockIdx.y;       // 0..63   (cols jBlk*64 ..)
    const int i      = rowBlk * THREADS + tid;
    const int j0     = jBlk * CHUNK;

    // same-spin if both halves match
    const int net = ((rowBlk < 8) == (jBlk < 32)) ? 0 : 1;

    // stage table (8 KB) into shared
    {
        const float4* src = (const float4*)g_tab[net];
        float4*       dst = (float4*)s_tab;
        #pragma unroll
        for (int t = tid; t < TBL / 4; t += THREADS) dst[t] = src[t];
    }
    // stage this chunk's j coordinates (packed xyz_)
    if (tid < CHUNK) {
        int j = j0 + tid;
        sj[tid] = make_float4(rs[3 * j + 0], rs[3 * j + 1], rs[3 * j + 2], 0.0f);
    }
    __syncthreads();

    const float xi = rs[3 * i + 0];
    const float yi = rs[3 * i + 1];
    const float zi = rs[3 * i + 2];

    float ax = 0.0f, ay = 0.0f, az = 0.0f;
    const float scale = (float)(TBL - 1) / SMAX;
    const float tmax  = (float)(TBL - 1) - 1e-3f;

    #pragma unroll 8
    for (int jj = 0; jj < CHUNK; jj++) {
        const float4 p = sj[jj];           // broadcast LDS.128
        float dx = xi - p.x;
        float dy = yi - p.y;
        float dz = zi - p.z;
        // minimum image: d -= BOX * rint(d / BOX)
        dx = fmaf(-BOX, rintf(dx * (1.0f / BOX)), dx);
        dy = fmaf(-BOX, rintf(dy * (1.0f / BOX)), dy);
        dz = fmaf(-BOX, rintf(dz * (1.0f / BOX)), dz);

        float s = fmaf(dx, dx, fmaf(dy, dy, dz * dz));
        // table lookup; beyond cutoff the clamped lerp lands on an exact 0.
        float t = fminf(s * scale, tmax);
        int   k = (int)t;
        float fr = t - (float)k;
        float2 tv = __half22float2(s_tab[k]);   // one LDS.32, conflict-light
        float f = fmaf(fr, tv.y, tv.x);

        ax = fmaf(f, dx, ax);
        ay = fmaf(f, dy, ay);
        az = fmaf(f, dz, az);
    }

    atomicAdd(&out[3 * i + 0], ax);
    atomicAdd(&out[3 * i + 1], ay);
    atomicAdd(&out[3 * i + 2], az);
}

extern "C" void kernel_launch(void* const* d_in, const int* in_sizes, int n_in,
                              void* d_out, int out_size) {
    const float* rs  = (const float*)d_in[0];
    const float* sw1 = (const float*)d_in[1];
    const float* sb1 = (const float*)d_in[2];
    const float* swo = (const float*)d_in[3];
    const float* sbo = (const float*)d_in[4];
    const float* dw1 = (const float*)d_in[5];
    const float* db1 = (const float*)d_in[6];
    const float* dwo = (const float*)d_in[7];
    const float* dbo = (const float*)d_in[8];
    float* out = (float*)d_out;

    // table warps: 2*TBL entries, 8 warps/CTA -> 512 CTAs, + 16 init CTAs
    const int buildGrid = INIT_CTAS + (2 * TBL) / (THREADS / 32);
    build_and_init<<<buildGrid, THREADS>>>(rs, out,
                                           sw1, sb1, swo, sbo,
                                           dw1, db1, dwo, dbo);

    dim3 grid(N_TOT / THREADS, N_TOT / CHUNK);   // (16, 64)
    backflow_kernel<<<grid, THREADS>>>(rs, out);
}

// round 5
// speedup vs baseline: 2.3844x; 1.0711x over previous
#include <cuda_runtime.h>
#include <cuda_fp16.h>
#include <math.h>

#define N_TOT   4096
#define N_UP    2048
#define HIDDEN  32
#define BOX     10.0f
#define TBL     2048
#define SMAX    25.0f        // r_cut^2 = 5^2
#define CHUNK   64
#define THREADS 128          // main kernel CTA size (rows per CTA)
#define BTHREADS 256         // build kernel CTA size
#define INIT_CTAS 16

#define MAGIC     12582912.0f        // 1.5 * 2^23
#define BASEBITS  0x4B400000u        // float bits of MAGIC
#define CAPBITS   (BASEBITS + (TBL - 1))

typedef unsigned long long u64;

// ---- packed f32x2 helpers (sm_103a; ptxas never emits these from C++) ----
__device__ __forceinline__ u64 pk2(float lo, float hi) {
    u64 r; asm("mov.b64 %0,{%1,%2};" : "=l"(r) : "f"(lo), "f"(hi)); return r;
}
__device__ __forceinline__ void upk2(u64 v, float& lo, float& hi) {
    asm("mov.b64 {%0,%1},%2;" : "=f"(lo), "=f"(hi) : "l"(v));
}
__device__ __forceinline__ u64 add2(u64 a, u64 b) {
    u64 r; asm("add.rn.f32x2 %0,%1,%2;" : "=l"(r) : "l"(a), "l"(b)); return r;
}
__device__ __forceinline__ u64 mul2(u64 a, u64 b) {
    u64 r; asm("mul.rn.f32x2 %0,%1,%2;" : "=l"(r) : "l"(a), "l"(b)); return r;
}
__device__ __forceinline__ u64 fma2(u64 a, u64 b, u64 c) {
    u64 r; asm("fma.rn.f32x2 %0,%1,%2,%3;" : "=l"(r) : "l"(a), "l"(b), "l"(c)); return r;
}

// Precomputed f(s) tables: [0]=same-spin net, [1]=diff-spin net.
// Each half2 entry: (value, slope-to-next-entry).
__device__ __align__(16) __half2 g_tab[2][TBL];

// ---------------------------------------------------------------------------
__device__ __forceinline__ float decay_of_s(float s) {
    float r  = sqrtf(s + 1e-15f);
    float xn = fminf(r * (1.0f / 5.0f), 1.0f - 1e-5f);
    float u  = 1.0f - xn * xn;
    return expf(1.0f - 1.0f / u);
}
__device__ __forceinline__ float unit_contrib(float decay, float w1, float b1, float wo) {
    float z = fmaf(decay, w1, b1);
    float h = z / (1.0f + expf(-z));
    return h * wo;
}

// Fused: build tables (warp per entry, lane per hidden unit) + out=rs init.
__global__ void __launch_bounds__(BTHREADS)
build_and_init(const float* __restrict__ rs, float* __restrict__ out,
               const float* __restrict__ sw1, const float* __restrict__ sb1,
               const float* __restrict__ swo, const float* __restrict__ sbo,
               const float* __restrict__ dw1, const float* __restrict__ db1,
               const float* __restrict__ dwo, const float* __restrict__ dbo) {
    const int bid = blockIdx.x;
    const int tid = threadIdx.x;

    if (bid < INIT_CTAS) {
        for (int i = bid * BTHREADS + tid; i < N_TOT * 3; i += INIT_CTAS * BTHREADS)
            out[i] = rs[i];
        return;
    }

    const int wglob = (bid - INIT_CTAS) * (BTHREADS / 32) + (tid >> 5);
    if (wglob >= 2 * TBL) return;
    const int net  = wglob / TBL;
    const int k    = wglob % TBL;
    const int lane = tid & 31;

    const float w1 = net ? dw1[lane] : sw1[lane];
    const float b1 = net ? db1[lane] : sb1[lane];
    const float wo = net ? dwo[lane] : swo[lane];
    const float bo = net ? dbo[0]    : sbo[0];

    const float h = SMAX / (float)(TBL - 1);
    const float d0 = decay_of_s((float)k * h);
    const float d1 = decay_of_s((float)(k + 1) * h);   // k=TBL-1 -> decay 0 -> (0,0)

    float a0 = unit_contrib(d0, w1, b1, wo);
    float a1 = unit_contrib(d1, w1, b1, wo);
    #pragma unroll
    for (int off = 16; off > 0; off >>= 1) {
        a0 += __shfl_xor_sync(0xFFFFFFFFu, a0, off);
        a1 += __shfl_xor_sync(0xFFFFFFFFu, a1, off);
    }
    if (lane == 0) {
        float f0 = (a0 + bo) * d0;
        float f1 = (a1 + bo) * d1;
        g_tab[net][k] = __floats2half2_rn(f0, f1 - f0);
    }
}

// ---------------------------------------------------------------------------
// Main pairwise kernel: grid (32 row blocks x 64 j-chunks) = 2048 CTAs.
// Each thread owns row i; each iteration handles TWO j's via f32x2 packing.
// ---------------------------------------------------------------------------
__global__ void __launch_bounds__(THREADS)
backflow_kernel(const float* __restrict__ rs, float* __restrict__ out) {
    __shared__ __align__(16) __half2 s_tab[TBL];          // 8 KB
    __shared__ __align__(16) float sjx[CHUNK];            // NEGATED j coords
    __shared__ __align__(16) float sjy[CHUNK];
    __shared__ __align__(16) float sjz[CHUNK];

    const int tid    = threadIdx.x;
    const int rowBlk = blockIdx.x;       // 0..31 (128 rows each)
    const int jBlk   = blockIdx.y;       // 0..63 (64 cols each)
    const int i      = rowBlk * THREADS + tid;
    const int j0     = jBlk * CHUNK;

    const int net = ((rowBlk < 16) == (jBlk < 32)) ? 0 : 1;

    // stage table (8 KB): 512 float4 over 128 threads
    {
        const float4* src = (const float4*)g_tab[net];
        float4*       dst = (float4*)s_tab;
        #pragma unroll
        for (int t = tid; t < TBL / 4; t += THREADS) dst[t] = src[t];
    }
    if (tid < CHUNK) {
        int j = j0 + tid;
        sjx[tid] = -rs[3 * j + 0];
        sjy[tid] = -rs[3 * j + 1];
        sjz[tid] = -rs[3 * j + 2];
    }
    __syncthreads();

    const float xi = rs[3 * i + 0];
    const float yi = rs[3 * i + 1];
    const float zi = rs[3 * i + 2];
    const u64 xi2 = pk2(xi, xi);
    const u64 yi2 = pk2(yi, yi);
    const u64 zi2 = pk2(zi, zi);

    const float scale = (float)(TBL - 1) / SMAX;
    const u64 c_inv10 = pk2(0.1f, 0.1f);
    const u64 c_mag   = pk2(MAGIC, MAGIC);
    const u64 c_nmag  = pk2(-MAGIC, -MAGIC);
    const u64 c_n10   = pk2(-BOX, -BOX);
    const u64 c_scale = pk2(scale, scale);

    u64 ax2 = 0, ay2 = 0, az2 = 0;   // packed (0.0f, 0.0f)

    #pragma unroll 8
    for (int c = 0; c < CHUNK / 2; c++) {
        const u64 nx = *(const u64*)&sjx[2 * c];   // broadcast LDS.64
        const u64 ny = *(const u64*)&sjy[2 * c];
        const u64 nz = *(const u64*)&sjz[2 * c];

        u64 dx = add2(xi2, nx);
        u64 dy = add2(yi2, ny);
        u64 dz = add2(zi2, nz);

        // min image: d -= 10 * round(d/10), round via magic constant
        u64 mx = fma2(dx, c_inv10, c_mag);
        u64 my = fma2(dy, c_inv10, c_mag);
        u64 mz = fma2(dz, c_inv10, c_mag);
        dx = fma2(add2(mx, c_nmag), c_n10, dx);
        dy = fma2(add2(my, c_nmag), c_n10, dy);
        dz = fma2(add2(mz, c_nmag), c_n10, dz);

        u64 s2 = fma2(dx, dx, fma2(dy, dy, mul2(dz, dz)));
        u64 t2 = mul2(s2, c_scale);

        float t0, t1;
        upk2(t2, t0, t1);

        // index from magic-sum bits; clamp on integer pipe; signed-fr lerp
        float m0 = __fadd_rn(t0, MAGIC);
        float m1 = __fadd_rn(t1, MAGIC);
        unsigned kb0 = min(__float_as_uint(m0), CAPBITS);
        unsigned kb1 = min(__float_as_uint(m1), CAPBITS);
        float fr0 = __fadd_rn(t0, -__fadd_rn(m0, -MAGIC));
        float fr1 = __fadd_rn(t1, -__fadd_rn(m1, -MAGIC));
        float2 tv0 = __half22float2(s_tab[kb0 - BASEBITS]);
        float2 tv1 = __half22float2(s_tab[kb1 - BASEBITS]);
        float f0 = fmaf(fr0, tv0.y, tv0.x);
        float f1 = fmaf(fr1, tv1.y, tv1.x);

        const u64 f2 = pk2(f0, f1);
        ax2 = fma2(f2, dx, ax2);
        ay2 = fma2(f2, dy, ay2);
        az2 = fma2(f2, dz, az2);
    }

    float axl, axh, ayl, ayh, azl, azh;
    upk2(ax2, axl, axh);
    upk2(ay2, ayl, ayh);
    upk2(az2, azl, azh);

    atomicAdd(&out[3 * i + 0], axl + axh);
    atomicAdd(&out[3 * i + 1], ayl + ayh);
    atomicAdd(&out[3 * i + 2], azl + azh);
}

extern "C" void kernel_launch(void* const* d_in, const int* in_sizes, int n_in,
                              void* d_out, int out_size) {
    const float* rs  = (const float*)d_in[0];
    const float* sw1 = (const float*)d_in[1];
    const float* sb1 = (const float*)d_in[2];
    const float* swo = (const float*)d_in[3];
    const float* sbo = (const float*)d_in[4];
    const float* dw1 = (const float*)d_in[5];
    const float* db1 = (const float*)d_in[6];
    const float* dwo = (const float*)d_in[7];
    const float* dbo = (const float*)d_in[8];
    float* out = (float*)d_out;

    const int buildGrid = INIT_CTAS + (2 * TBL) / (BTHREADS / 32);
    build_and_init<<<buildGrid, BTHREADS>>>(rs, out,
                                            sw1, sb1, swo, sbo,
                                            dw1, db1, dwo, dbo);

    dim3 grid(N_TOT / THREADS, N_TOT / CHUNK);   // (32, 64)
    backflow_kernel<<<grid, THREADS>>>(rs, out);
}

// round 6
// speedup vs baseline: 2.4242x; 1.0167x over previous
#include <cuda_runtime.h>
#include <cuda_fp16.h>
#include <math.h>

#define N_TOT   4096
#define N_UP    2048
#define HIDDEN  32
#define BOX     10.0f
#define TBL     2048
#define SMAX    25.0f        // r_cut^2 = 5^2
#define CHUNK   128
#define THREADS 128          // main kernel CTA size (rows per CTA)
#define BTHREADS 256         // build kernel CTA size
#define INIT_CTAS 16

#define MAGIC     12582912.0f        // 1.5 * 2^23
#define BASEBITS  0x4B400000u        // float bits of MAGIC
#define CAPBITS   (BASEBITS + (TBL - 1))

typedef unsigned long long u64;

// ---- packed f32x2 helpers (sm_103a; ptxas never emits these from C++) ----
__device__ __forceinline__ u64 pk2(float lo, float hi) {
    u64 r; asm("mov.b64 %0,{%1,%2};" : "=l"(r) : "f"(lo), "f"(hi)); return r;
}
__device__ __forceinline__ void upk2(u64 v, float& lo, float& hi) {
    asm("mov.b64 {%0,%1},%2;" : "=f"(lo), "=f"(hi) : "l"(v));
}
__device__ __forceinline__ void upk2u(u64 v, unsigned& lo, unsigned& hi) {
    asm("mov.b64 {%0,%1},%2;" : "=r"(lo), "=r"(hi) : "l"(v));
}
__device__ __forceinline__ u64 add2(u64 a, u64 b) {
    u64 r; asm("add.rn.f32x2 %0,%1,%2;" : "=l"(r) : "l"(a), "l"(b)); return r;
}
__device__ __forceinline__ u64 mul2(u64 a, u64 b) {
    u64 r; asm("mul.rn.f32x2 %0,%1,%2;" : "=l"(r) : "l"(a), "l"(b)); return r;
}
__device__ __forceinline__ u64 fma2(u64 a, u64 b, u64 c) {
    u64 r; asm("fma.rn.f32x2 %0,%1,%2,%3;" : "=l"(r) : "l"(a), "l"(b), "l"(c)); return r;
}

// Precomputed f(s) tables, values pre-divided by the coordinate scale c.
// [0]=same-spin net, [1]=diff-spin net. half2 entry: (value, slope).
__device__ __align__(16) __half2 g_tab[2][TBL];

// ---------------------------------------------------------------------------
__device__ __forceinline__ float decay_of_s(float s) {
    float r  = sqrtf(s + 1e-15f);
    float xn = fminf(r * (1.0f / 5.0f), 1.0f - 1e-5f);
    float u  = 1.0f - xn * xn;
    return expf(1.0f - 1.0f / u);
}
__device__ __forceinline__ float unit_contrib(float decay, float w1, float b1, float wo) {
    float z = fmaf(decay, w1, b1);
    float h = z / (1.0f + expf(-z));
    return h * wo;
}

// Fused: build tables (warp per entry, lane per hidden unit) + out=rs init.
__global__ void __launch_bounds__(BTHREADS)
build_and_init(const float* __restrict__ rs, float* __restrict__ out,
               const float* __restrict__ sw1, const float* __restrict__ sb1,
               const float* __restrict__ swo, const float* __restrict__ sbo,
               const float* __restrict__ dw1, const float* __restrict__ db1,
               const float* __restrict__ dwo, const float* __restrict__ dbo) {
    const int bid = blockIdx.x;
    const int tid = threadIdx.x;

    if (bid < INIT_CTAS) {
        for (int i = bid * BTHREADS + tid; i < N_TOT * 3; i += INIT_CTAS * BTHREADS)
            out[i] = rs[i];
        return;
    }

    const int wglob = (bid - INIT_CTAS) * (BTHREADS / 32) + (tid >> 5);
    if (wglob >= 2 * TBL) return;
    const int net  = wglob / TBL;
    const int k    = wglob % TBL;
    const int lane = tid & 31;

    const float w1 = net ? dw1[lane] : sw1[lane];
    const float b1 = net ? db1[lane] : sb1[lane];
    const float wo = net ? dwo[lane] : swo[lane];
    const float bo = net ? dbo[0]    : sbo[0];

    const float h = SMAX / (float)(TBL - 1);
    const float d0 = decay_of_s((float)k * h);
    const float d1 = decay_of_s((float)(k + 1) * h);   // k=TBL-1 -> decay 0 -> (0,0)

    float a0 = unit_contrib(d0, w1, b1, wo);
    float a1 = unit_contrib(d1, w1, b1, wo);
    #pragma unroll
    for (int off = 16; off > 0; off >>= 1) {
        a0 += __shfl_xor_sync(0xFFFFFFFFu, a0, off);
        a1 += __shfl_xor_sync(0xFFFFFFFFu, a1, off);
    }
    if (lane == 0) {
        const float cs = sqrtf((float)(TBL - 1) / SMAX);   // coord scale
        float f0 = (a0 + bo) * d0 / cs;
        float f1 = (a1 + bo) * d1 / cs;
        g_tab[net][k] = __floats2half2_rn(f0, f1 - f0);
    }
}

// ---------------------------------------------------------------------------
// Main pairwise kernel: grid (32 row blocks x 32 j-chunks) = 1024 CTAs —
// a SINGLE wave (~7 CTAs/SM, all resident). Coordinates pre-scaled so that
// t = |d'|^2 is the table coordinate directly. Two j's per iter via f32x2.
// ---------------------------------------------------------------------------
__global__ void __launch_bounds__(THREADS)
backflow_kernel(const float* __restrict__ rs, float* __restrict__ out) {
    __shared__ __align__(16) __half2 s_tab[TBL];          // 8 KB
    __shared__ __align__(16) float sjx[CHUNK];            // NEGATED, scaled j coords
    __shared__ __align__(16) float sjy[CHUNK];
    __shared__ __align__(16) float sjz[CHUNK];

    const int tid    = threadIdx.x;
    const int rowBlk = blockIdx.x;       // 0..31 (128 rows each)
    const int jBlk   = blockIdx.y;       // 0..31 (128 cols each)
    const int i      = rowBlk * THREADS + tid;
    const int j0     = jBlk * CHUNK;

    const int net = ((rowBlk < 16) == (jBlk < 16)) ? 0 : 1;

    const float cs   = sqrtf((float)(TBL - 1) / SMAX);   // coord scale
    const float BOXS = BOX * cs;

    // stage table (8 KB): 512 float4 over 128 threads
    {
        const float4* src = (const float4*)g_tab[net];
        float4*       dst = (float4*)s_tab;
        #pragma unroll
        for (int t = tid; t < TBL / 4; t += THREADS) dst[t] = src[t];
    }
    {
        int j = j0 + tid;
        sjx[tid] = -cs * rs[3 * j + 0];
        sjy[tid] = -cs * rs[3 * j + 1];
        sjz[tid] = -cs * rs[3 * j + 2];
    }
    __syncthreads();

    const float xi = cs * rs[3 * i + 0];
    const float yi = cs * rs[3 * i + 1];
    const float zi = cs * rs[3 * i + 2];
    const u64 xi2 = pk2(xi, xi);
    const u64 yi2 = pk2(yi, yi);
    const u64 zi2 = pk2(zi, zi);

    const u64 c_invb = pk2(1.0f / BOXS, 1.0f / BOXS);
    const u64 c_mag  = pk2(MAGIC, MAGIC);
    const u64 c_nmag = pk2(-MAGIC, -MAGIC);
    const u64 c_nb   = pk2(-BOXS, -BOXS);
    const u64 c_neg1 = pk2(-1.0f, -1.0f);

    u64 ax2 = 0, ay2 = 0, az2 = 0;   // packed (0.0f, 0.0f)

    #pragma unroll 8
    for (int c = 0; c < CHUNK / 2; c++) {
        const u64 nx = *(const u64*)&sjx[2 * c];   // broadcast LDS.64
        const u64 ny = *(const u64*)&sjy[2 * c];
        const u64 nz = *(const u64*)&sjz[2 * c];

        u64 dx = add2(xi2, nx);
        u64 dy = add2(yi2, ny);
        u64 dz = add2(zi2, nz);

        // min image (scaled box): d -= BOXS * round(d/BOXS) via magic constant
        u64 mx = fma2(dx, c_invb, c_mag);
        u64 my = fma2(dy, c_invb, c_mag);
        u64 mz = fma2(dz, c_invb, c_mag);
        dx = fma2(add2(mx, c_nmag), c_nb, dx);
        dy = fma2(add2(my, c_nmag), c_nb, dy);
        dz = fma2(add2(mz, c_nmag), c_nb, dz);

        // t = |d'|^2 is the table coordinate directly
        u64 t2 = fma2(dx, dx, fma2(dy, dy, mul2(dz, dz)));

        // packed round -> index bits + signed fraction
        u64 m2  = add2(t2, c_mag);
        u64 r2  = add2(m2, c_nmag);
        u64 fr2 = fma2(r2, c_neg1, t2);

        unsigned kb0, kb1;
        upk2u(m2, kb0, kb1);
        kb0 = min(kb0, CAPBITS);
        kb1 = min(kb1, CAPBITS);
        float fr0, fr1;
        upk2(fr2, fr0, fr1);

        float2 tv0 = __half22float2(s_tab[kb0 - BASEBITS]);
        float2 tv1 = __half22float2(s_tab[kb1 - BASEBITS]);
        float f0 = fmaf(fr0, tv0.y, tv0.x);
        float f1 = fmaf(fr1, tv1.y, tv1.x);

        const u64 f2 = pk2(f0, f1);
        ax2 = fma2(f2, dx, ax2);
        ay2 = fma2(f2, dy, ay2);
        az2 = fma2(f2, dz, az2);
    }

    float axl, axh, ayl, ayh, azl, azh;
    upk2(ax2, axl, axh);
    upk2(ay2, ayl, ayh);
    upk2(az2, azl, azh);

    atomicAdd(&out[3 * i + 0], axl + axh);
    atomicAdd(&out[3 * i + 1], ayl + ayh);
    atomicAdd(&out[3 * i + 2], azl + azh);
}

extern "C" void kernel_launch(void* const* d_in, const int* in_sizes, int n_in,
                              void* d_out, int out_size) {
    const float* rs  = (const float*)d_in[0];
    const float* sw1 = (const float*)d_in[1];
    const float* sb1 = (const float*)d_in[2];
    const float* swo = (const float*)d_in[3];
    const float* sbo = (const float*)d_in[4];
    const float* dw1 = (const float*)d_in[5];
    const float* db1 = (const float*)d_in[6];
    const float* dwo = (const float*)d_in[7];
    const float* dbo = (const float*)d_in[8];
    float* out = (float*)d_out;

    const int buildGrid = INIT_CTAS + (2 * TBL) / (BTHREADS / 32);
    build_and_init<<<buildGrid, BTHREADS>>>(rs, out,
                                            sw1, sb1, swo, sbo,
                                            dw1, db1, dwo, dbo);

    dim3 grid(N_TOT / THREADS, N_TOT / CHUNK);   // (32, 32) — single wave
    backflow_kernel<<<grid, THREADS>>>(rs, out);
}

// round 7
// speedup vs baseline: 2.9492x; 1.2166x over previous
#include <cuda_runtime.h>
#include <math.h>

#define N_TOT   4096
#define N_UP    2048
#define HIDDEN  32
#define BOX     10.0f
#define TBL     4096
#define SMAX    25.0f        // r_cut^2 = 5^2
#define CHUNK   64
#define THREADS 256          // main kernel CTA size (rows per CTA)
#define BTHREADS 256         // build kernel CTA size
#define INIT_CTAS 16

#define MAGIC     12582912.0f        // 1.5 * 2^23
#define BASEBITS  0x4B400000u        // float bits of MAGIC
#define CAPBITS   (BASEBITS + (TBL - 1))

typedef unsigned long long u64;

// ---- packed f32x2 helpers (sm_103a; ptxas never emits these from C++) ----
__device__ __forceinline__ u64 pk2(float lo, float hi) {
    u64 r; asm("mov.b64 %0,{%1,%2};" : "=l"(r) : "f"(lo), "f"(hi)); return r;
}
__device__ __forceinline__ void upk2u(u64 v, unsigned& lo, unsigned& hi) {
    asm("mov.b64 {%0,%1},%2;" : "=r"(lo), "=r"(hi) : "l"(v));
}
__device__ __forceinline__ void upk2(u64 v, float& lo, float& hi) {
    asm("mov.b64 {%0,%1},%2;" : "=f"(lo), "=f"(hi) : "l"(v));
}
__device__ __forceinline__ u64 add2(u64 a, u64 b) {
    u64 r; asm("add.rn.f32x2 %0,%1,%2;" : "=l"(r) : "l"(a), "l"(b)); return r;
}
__device__ __forceinline__ u64 mul2(u64 a, u64 b) {
    u64 r; asm("mul.rn.f32x2 %0,%1,%2;" : "=l"(r) : "l"(a), "l"(b)); return r;
}
__device__ __forceinline__ u64 fma2(u64 a, u64 b, u64 c) {
    u64 r; asm("fma.rn.f32x2 %0,%1,%2,%3;" : "=l"(r) : "l"(a), "l"(b), "l"(c)); return r;
}

// Precomputed f(s) tables (values pre-divided by coord scale cs).
// Nearest-neighbor lookup: plain float entries. [0]=same, [1]=diff.
__device__ __align__(16) float g_tab[2][TBL];

// ---------------------------------------------------------------------------
__device__ __forceinline__ float decay_of_s(float s) {
    float r  = sqrtf(s + 1e-15f);
    float xn = fminf(r * (1.0f / 5.0f), 1.0f - 1e-5f);
    float u  = 1.0f - xn * xn;
    return expf(1.0f - 1.0f / u);
}
__device__ __forceinline__ float unit_contrib(float decay, float w1, float b1, float wo) {
    float z = fmaf(decay, w1, b1);
    float h = z / (1.0f + expf(-z));
    return h * wo;
}

// Fused: build tables (warp per entry, lane per hidden unit) + out=rs init.
__global__ void __launch_bounds__(BTHREADS)
build_and_init(const float* __restrict__ rs, float* __restrict__ out,
               const float* __restrict__ sw1, const float* __restrict__ sb1,
               const float* __restrict__ swo, const float* __restrict__ sbo,
               const float* __restrict__ dw1, const float* __restrict__ db1,
               const float* __restrict__ dwo, const float* __restrict__ dbo) {
    const int bid = blockIdx.x;
    const int tid = threadIdx.x;

    if (bid < INIT_CTAS) {
        for (int i = bid * BTHREADS + tid; i < N_TOT * 3; i += INIT_CTAS * BTHREADS)
            out[i] = rs[i];
        return;
    }

    const int wglob = (bid - INIT_CTAS) * (BTHREADS / 32) + (tid >> 5);
    if (wglob >= 2 * TBL) return;
    const int net  = wglob / TBL;
    const int k    = wglob % TBL;
    const int lane = tid & 31;

    const float w1 = net ? dw1[lane] : sw1[lane];
    const float b1 = net ? db1[lane] : sb1[lane];
    const float wo = net ? dwo[lane] : swo[lane];
    const float bo = net ? dbo[0]    : sbo[0];

    const float h = SMAX / (float)(TBL - 1);
    const float d0 = decay_of_s((float)k * h);

    float a0 = unit_contrib(d0, w1, b1, wo);
    #pragma unroll
    for (int off = 16; off > 0; off >>= 1)
        a0 += __shfl_xor_sync(0xFFFFFFFFu, a0, off);
    if (lane == 0) {
        const float cs = sqrtf((float)(TBL - 1) / SMAX);   // coord scale
        g_tab[net][k] = (a0 + bo) * d0 / cs;
    }
}

// ---------------------------------------------------------------------------
// Main pairwise kernel: grid (16 row blocks x 64 j-chunks) = 1024 CTAs,
// 256 threads (~6 resident CTAs/SM = 48 warps). Coordinates pre-scaled so
// t = |d'|^2 is the table coordinate; nearest-entry lookup (no lerp).
// Two j's per iteration via f32x2 packing.
// ---------------------------------------------------------------------------
__global__ void __launch_bounds__(THREADS)
backflow_kernel(const float* __restrict__ rs, float* __restrict__ out) {
    __shared__ __align__(16) float s_tab[TBL];            // 16 KB
    __shared__ __align__(16) float sjx[CHUNK];            // NEGATED, scaled j coords
    __shared__ __align__(16) float sjy[CHUNK];
    __shared__ __align__(16) float sjz[CHUNK];

    const int tid    = threadIdx.x;
    const int rowBlk = blockIdx.x;       // 0..15 (256 rows each)
    const int jBlk   = blockIdx.y;       // 0..63 (64 cols each)
    const int i      = rowBlk * THREADS + tid;
    const int j0     = jBlk * CHUNK;

    const int net = ((rowBlk < 8) == (jBlk < 32)) ? 0 : 1;

    const float cs   = sqrtf((float)(TBL - 1) / SMAX);   // coord scale
    const float BOXS = BOX * cs;

    // stage table (16 KB): 1024 float4 over 256 threads
    {
        const float4* src = (const float4*)g_tab[net];
        float4*       dst = (float4*)s_tab;
        #pragma unroll
        for (int t = tid; t < TBL / 4; t += THREADS) dst[t] = src[t];
    }
    if (tid < CHUNK) {
        int j = j0 + tid;
        sjx[tid] = -cs * rs[3 * j + 0];
        sjy[tid] = -cs * rs[3 * j + 1];
        sjz[tid] = -cs * rs[3 * j + 2];
    }
    __syncthreads();

    const float xi = cs * rs[3 * i + 0];
    const float yi = cs * rs[3 * i + 1];
    const float zi = cs * rs[3 * i + 2];
    const u64 xi2 = pk2(xi, xi);
    const u64 yi2 = pk2(yi, yi);
    const u64 zi2 = pk2(zi, zi);

    const u64 c_invb = pk2(1.0f / BOXS, 1.0f / BOXS);
    const u64 c_mag  = pk2(MAGIC, MAGIC);
    const u64 c_nmag = pk2(-MAGIC, -MAGIC);
    const u64 c_nb   = pk2(-BOXS, -BOXS);

    u64 ax2 = 0, ay2 = 0, az2 = 0;   // packed (0.0f, 0.0f)

    #pragma unroll 8
    for (int c = 0; c < CHUNK / 2; c++) {
        const u64 nx = *(const u64*)&sjx[2 * c];   // broadcast LDS.64
        const u64 ny = *(const u64*)&sjy[2 * c];
        const u64 nz = *(const u64*)&sjz[2 * c];

        u64 dx = add2(xi2, nx);
        u64 dy = add2(yi2, ny);
        u64 dz = add2(zi2, nz);

        // min image (scaled box): d -= BOXS * round(d/BOXS) via magic constant
        u64 mx = fma2(dx, c_invb, c_mag);
        u64 my = fma2(dy, c_invb, c_mag);
        u64 mz = fma2(dz, c_invb, c_mag);
        dx = fma2(add2(mx, c_nmag), c_nb, dx);
        dy = fma2(add2(my, c_nmag), c_nb, dy);
        dz = fma2(add2(mz, c_nmag), c_nb, dz);

        // t = |d'|^2 is the table coordinate; nearest index via magic bits
        u64 t2 = fma2(dx, dx, fma2(dy, dy, mul2(dz, dz)));
        u64 m2 = add2(t2, c_mag);

        unsigned kb0, kb1;
        upk2u(m2, kb0, kb1);
        kb0 = min(kb0, CAPBITS);
        kb1 = min(kb1, CAPBITS);

        float f0 = s_tab[kb0 - BASEBITS];
        float f1 = s_tab[kb1 - BASEBITS];

        const u64 f2 = pk2(f0, f1);
        ax2 = fma2(f2, dx, ax2);
        ay2 = fma2(f2, dy, ay2);
        az2 = fma2(f2, dz, az2);
    }

    float axl, axh, ayl, ayh, azl, azh;
    upk2(ax2, axl, axh);
    upk2(ay2, ayl, ayh);
    upk2(az2, azl, azh);

    atomicAdd(&out[3 * i + 0], axl + axh);
    atomicAdd(&out[3 * i + 1], ayl + ayh);
    atomicAdd(&out[3 * i + 2], azl + azh);
}

extern "C" void kernel_launch(void* const* d_in, const int* in_sizes, int n_in,
                              void* d_out, int out_size) {
    const float* rs  = (const float*)d_in[0];
    const float* sw1 = (const float*)d_in[1];
    const float* sb1 = (const float*)d_in[2];
    const float* swo = (const float*)d_in[3];
    const float* sbo = (const float*)d_in[4];
    const float* dw1 = (const float*)d_in[5];
    const float* db1 = (const float*)d_in[6];
    const float* dwo = (const float*)d_in[7];
    const float* dbo = (const float*)d_in[8];
    float* out = (float*)d_out;

    const int buildGrid = INIT_CTAS + (2 * TBL) / (BTHREADS / 32);
    build_and_init<<<buildGrid, BTHREADS>>>(rs, out,
                                            sw1, sb1, swo, sbo,
                                            dw1, db1, dwo, dbo);

    dim3 grid(N_TOT / THREADS, N_TOT / CHUNK);   // (16, 64) — single wave
    backflow_kernel<<<grid, THREADS>>>(rs, out);
}